// round 2
// baseline (speedup 1.0000x reference)
#include <cuda_runtime.h>

// NoReFT intervention on [B, 768] fp32, 4 fixed 16-wide regions.
// STARTS = (0, 752, 184, 568); float4-starts {0, 188, 46, 142}.
// Row = 192 float4 = 6 warps:
//   warp 0 -> group 0 @ lane 0
//   warp 1 -> group 2 @ lane 14
//   warp 4 -> group 3 @ lane 14
//   warp 5 -> group 1 @ lane 28
// Folded edit: out = x + M_g^T x + c_g on the 16 region channels.

#define ROW_F4 192
#define KROWS 4
#define NTHREADS ROW_F4

__global__ __launch_bounds__(NTHREADS) void minireft_kernel(
    const float4* __restrict__ in, float4* __restrict__ out,
    const float* __restrict__ Wp, const float* __restrict__ bp,
    const float* __restrict__ Ws, const float* __restrict__ bs,
    int B)
{
    __shared__ float sM[4][16][16];  // sM[g][e_in][e_out]
    __shared__ float sC[4][16];

    const int tid = threadIdx.x;

    for (int idx = tid; idx < 4 * 16 * 16; idx += NTHREADS) {
        int g = idx >> 8, ep = (idx >> 4) & 15, e = idx & 15;
        float acc = 0.f;
        #pragma unroll
        for (int r = 0; r < 8; r++) {
            float wp_ep = Wp[g * 128 + r * 16 + ep];
            float ws_ep = Ws[g * 128 + r * 16 + ep];
            acc += (ws_ep - wp_ep) * Wp[g * 128 + r * 16 + e];
        }
        sM[g][ep][e] = acc;
    }
    for (int idx = tid; idx < 4 * 16; idx += NTHREADS) {
        int g = idx >> 4, e = idx & 15;
        float acc = 0.f;
        #pragma unroll
        for (int r = 0; r < 8; r++)
            acc += (bs[g * 8 + r] - bp[g * 8 + r]) * Wp[g * 128 + r * 16 + e];
        sC[g][e] = acc;
    }
    __syncthreads();

    const int chunk = tid;          // float4 index within the row
    const int wrow  = chunk >> 5;   // warp within row (0..5)
    const int lane  = chunk & 31;

    int g = -1, base = 0;
    if      (wrow == 0) { g = 0; base = 0;  }
    else if (wrow == 1) { g = 2; base = 14; }
    else if (wrow == 4) { g = 3; base = 14; }
    else if (wrow == 5) { g = 1; base = 28; }

    const long long rowStride = (long long)gridDim.x * KROWS;
    const long long step      = rowStride * ROW_F4;

    long long row0 = (long long)blockIdx.x * KROWS;
    const float4* ip = in  + row0 * ROW_F4 + chunk;
    float4*       op = out + row0 * ROW_F4 + chunk;

    for (; row0 < B; row0 += rowStride, ip += step, op += step) {
        // Front-batched loads: 4 independent LDG.128 in flight per thread.
        float4 v0 = __ldcs(ip + 0 * ROW_F4);
        float4 v1 = __ldcs(ip + 1 * ROW_F4);
        float4 v2 = __ldcs(ip + 2 * ROW_F4);
        float4 v3 = __ldcs(ip + 3 * ROW_F4);

        if (g >= 0) {
            const int off = lane - base;
            const bool hit = (off >= 0 && off < 4);
            const int j = hit ? (off * 4) : 0;

            #pragma unroll
            for (int k = 0; k < KROWS; k++) {
                float4& v = (k == 0) ? v0 : (k == 1) ? v1 : (k == 2) ? v2 : v3;
                float x[16];
                #pragma unroll
                for (int q = 0; q < 4; q++) {
                    x[4 * q + 0] = __shfl_sync(0xffffffffu, v.x, base + q);
                    x[4 * q + 1] = __shfl_sync(0xffffffffu, v.y, base + q);
                    x[4 * q + 2] = __shfl_sync(0xffffffffu, v.z, base + q);
                    x[4 * q + 3] = __shfl_sync(0xffffffffu, v.w, base + q);
                }
                if (hit) {
                    float d0 = sC[g][j + 0];
                    float d1 = sC[g][j + 1];
                    float d2 = sC[g][j + 2];
                    float d3 = sC[g][j + 3];
                    #pragma unroll
                    for (int e = 0; e < 16; e++) {
                        const float xe = x[e];
                        d0 += sM[g][e][j + 0] * xe;
                        d1 += sM[g][e][j + 1] * xe;
                        d2 += sM[g][e][j + 2] * xe;
                        d3 += sM[g][e][j + 3] * xe;
                    }
                    v.x += d0; v.y += d1; v.z += d2; v.w += d3;
                }
            }
        }

        __stcs(op + 0 * ROW_F4, v0);
        __stcs(op + 1 * ROW_F4, v1);
        __stcs(op + 2 * ROW_F4, v2);
        __stcs(op + 3 * ROW_F4, v3);
    }
}

extern "C" void kernel_launch(void* const* d_in, const int* in_sizes, int n_in,
                              void* d_out, int out_size)
{
    const float* base = (const float*)d_in[0];  // [1, B, 768]
    const float* Wp   = (const float*)d_in[1];  // [4, 8, 16]
    const float* bp   = (const float*)d_in[2];  // [4, 8]
    const float* Ws   = (const float*)d_in[3];  // [4, 8, 16]
    const float* bs   = (const float*)d_in[4];  // [4, 8]
    float* out = (float*)d_out;

    const int B = in_sizes[0] / 768;  // 131072 (multiple of KROWS)

    int grid = (B + KROWS - 1) / KROWS;
    if (grid > 2048) grid = 2048;

    minireft_kernel<<<grid, NTHREADS>>>(
        (const float4*)base, (float4*)out, Wp, bp, Ws, bs, B);
}

// round 3
// speedup vs baseline: 1.0618x; 1.0618x over previous
#include <cuda_runtime.h>

// NoReFT on [B,768] fp32. Regions: starts {0, 752, 184, 568}, width 16.
// float4 chunk indices per row covered by regions:
//   {0..3}, {188..191}, {46..49}, {142..145}
//
// Decoupled design:
//   blocks [0, FIX_BLOCKS): region fixup, out_region = x + M_g x + c_g (reads base only)
//   blocks [FIX_BLOCKS, ..): pure float4 copy of the other 176 chunks per row
// Outputs are disjoint -> no ordering needed.

#define FIX_BLOCKS 128
#define COPY_BLOCKS 2048
#define NT 384

__global__ __launch_bounds__(NT, 4) void minireft_kernel(
    const float* __restrict__ base, float* __restrict__ out,
    const float* __restrict__ Wp, const float* __restrict__ bp,
    const float* __restrict__ Ws, const float* __restrict__ bs,
    int B)
{
    if (blockIdx.x < FIX_BLOCKS) {
        // ---------------- region fixup ----------------
        const int w    = threadIdx.x >> 5;   // 0..11
        const int lane = threadIdx.x & 31;
        const int g    = w & 3;              // region id for this warp
        const int half = lane >> 4;          // 0/1: which row of the pair
        const int l    = lane & 15;          // output channel within region
        const int shflBase = lane & 16;

        const int start = (g == 0) ? 0 : (g == 1) ? 752 : (g == 2) ? 184 : 568;

        // M column l and bias c_l for region g, kept in registers.
        float Mv[16];
        #pragma unroll
        for (int e = 0; e < 16; e++) {
            float acc = 0.f;
            #pragma unroll
            for (int r = 0; r < 8; r++) {
                float wp = Wp[g * 128 + r * 16 + e];
                float ws = Ws[g * 128 + r * 16 + e];
                acc += (ws - wp) * Wp[g * 128 + r * 16 + l];
            }
            Mv[e] = acc;
        }
        float cv = 0.f;
        #pragma unroll
        for (int r = 0; r < 8; r++)
            cv += (bs[g * 8 + r] - bp[g * 8 + r]) * Wp[g * 128 + r * 16 + l];

        // Each warp streams row-pairs: rows 2*rp + half.
        const long long nPairs = ((long long)B + 1) >> 1;
        const long long stride = (long long)FIX_BLOCKS * 3;   // 3 pair-streams/block per g
        long long rp = (long long)blockIdx.x * 3 + (w >> 2);

        for (; rp < nPairs; rp += 2 * stride) {
            const long long rowA = 2 * rp + half;
            const long long rpB  = rp + stride;
            const long long rowB = 2 * rpB + half;

            const bool okA = rowA < B;
            const bool okB = (rpB < nPairs) && (rowB < B);

            float xA = okA ? __ldcs(base + rowA * 768 + start + l) : 0.f;
            float xB = okB ? __ldcs(base + rowB * 768 + start + l) : 0.f;

            float dA = cv, dB = cv;
            #pragma unroll
            for (int e = 0; e < 16; e++) {
                dA += Mv[e] * __shfl_sync(0xffffffffu, xA, shflBase + e);
                dB += Mv[e] * __shfl_sync(0xffffffffu, xB, shflBase + e);
            }
            if (okA) __stcs(out + rowA * 768 + start + l, xA + dA);
            if (okB) __stcs(out + rowB * 768 + start + l, xB + dB);
        }
    } else {
        // ---------------- pure streaming copy ----------------
        const int bid   = blockIdx.x - FIX_BLOCKS;
        const int tid   = threadIdx.x;
        const int chunk = tid % 192;          // float4 index within row
        const int ry    = tid / 192;          // 0/1

        const bool masked = (chunk < 4) ||
                            (chunk >= 46 && chunk < 50) ||
                            (chunk >= 142 && chunk < 146) ||
                            (chunk >= 188);
        if (masked) return;  // region chunks handled by fixup blocks

        const float4* inp = (const float4*)base;
        float4* outp = (float4*)out;

        const long long S = (long long)COPY_BLOCKS * 2;       // rows per wave
        long long row = (long long)bid * 2 + ry;

        for (; row + S < B; row += 2 * S) {
            float4 v0 = __ldcs(inp + row * 192 + chunk);
            float4 v1 = __ldcs(inp + (row + S) * 192 + chunk);
            __stcs(outp + row * 192 + chunk, v0);
            __stcs(outp + (row + S) * 192 + chunk, v1);
        }
        for (; row < B; row += S) {
            float4 v = __ldcs(inp + row * 192 + chunk);
            __stcs(outp + row * 192 + chunk, v);
        }
    }
}

extern "C" void kernel_launch(void* const* d_in, const int* in_sizes, int n_in,
                              void* d_out, int out_size)
{
    const float* base = (const float*)d_in[0];  // [1, B, 768]
    const float* Wp   = (const float*)d_in[1];  // [4, 8, 16]
    const float* bp   = (const float*)d_in[2];  // [4, 8]
    const float* Ws   = (const float*)d_in[3];  // [4, 8, 16]
    const float* bs   = (const float*)d_in[4];  // [4, 8]
    float* out = (float*)d_out;

    const int B = in_sizes[0] / 768;

    minireft_kernel<<<FIX_BLOCKS + COPY_BLOCKS, NT>>>(
        base, out, Wp, bp, Ws, bs, B);
}

// round 4
// speedup vs baseline: 1.2393x; 1.1673x over previous
#include <cuda_runtime.h>
#include <cstdint>

// NoReFT on [B,768] fp32, 4 fixed 16-wide regions (starts 0,752,184,568).
// TMA bulk-load pipeline: 24KB tiles (8 rows) -> smem ring (3 stages),
// fixup applied in/from smem, coalesced STG.128 out.

#define T_ROWS 8
#define TILE_F (T_ROWS * 768)          // 6144 floats
#define TILE_F4 (TILE_F / 4)           // 1536 float4
#define TILE_BYTES (TILE_F * 4)        // 24576 bytes
#define STAGES 3
#define NT 384
#define MAXGRID 2048

// smem float offsets
#define SM_BUF 0
#define SM_M   (STAGES * TILE_F)                 // 18432
#define SM_C   (SM_M + 4 * 16 * 16)              // 19456
#define SM_BAR (SM_C + 64)                       // 19520 -> byte 78080 (8B aligned)
#define SM_BYTES (SM_BAR * 4 + STAGES * 8)       // 78104

__device__ __forceinline__ void mbar_init(uint32_t a, uint32_t cnt) {
    asm volatile("mbarrier.init.shared.b64 [%0], %1;" :: "r"(a), "r"(cnt) : "memory");
}
__device__ __forceinline__ void mbar_expect_tx(uint32_t a, uint32_t bytes) {
    asm volatile("mbarrier.arrive.expect_tx.shared.b64 _, [%0], %1;" :: "r"(a), "r"(bytes) : "memory");
}
__device__ __forceinline__ void mbar_wait(uint32_t a, uint32_t parity) {
    asm volatile(
        "{\n\t.reg .pred P;\n\t"
        "LW_%=:\n\t"
        "mbarrier.try_wait.parity.acquire.cta.shared::cta.b64 P, [%0], %1, 0x989680;\n\t"
        "@P bra LD_%=;\n\t"
        "bra LW_%=;\n\t"
        "LD_%=:\n\t}"
        :: "r"(a), "r"(parity) : "memory");
}
__device__ __forceinline__ void bulk_ld(uint32_t dst, const void* src, uint32_t bytes, uint32_t bar) {
    asm volatile("cp.async.bulk.shared::cta.global.mbarrier::complete_tx::bytes [%0], [%1], %2, [%3];"
                 :: "r"(dst), "l"(src), "r"(bytes), "r"(bar) : "memory");
}

__device__ __forceinline__ int region_of(int c4, int& off) {
    if (c4 < 4)                 { off = c4;       return 0; }
    if (c4 >= 188)              { off = c4 - 188; return 1; }
    if (c4 >= 46 && c4 < 50)    { off = c4 - 46;  return 2; }
    if (c4 >= 142 && c4 < 146)  { off = c4 - 142; return 3; }
    off = 0; return -1;
}
__device__ __forceinline__ int start4_of(int g) {
    return g == 0 ? 0 : g == 1 ? 188 : g == 2 ? 46 : 142;
}

__global__ __launch_bounds__(NT) void minireft_tma(
    const float* __restrict__ base, float* __restrict__ out,
    const float* __restrict__ Wp, const float* __restrict__ bp,
    const float* __restrict__ Ws, const float* __restrict__ bs,
    int B, int nTiles, int grid)
{
    extern __shared__ float smem[];
    float* sM = smem + SM_M;   // [4][16][16]: sM[(g*16+e)*16+l]
    float* sC = smem + SM_C;   // [4][16]
    const uint32_t smem_base = (uint32_t)__cvta_generic_to_shared(smem);
    const uint32_t bar0 = smem_base + SM_BAR * 4;

    const int tid = threadIdx.x;

    // ---- fold weights: M[g][e][l], C[g][l] ----
    for (int idx = tid; idx < 4 * 16 * 16; idx += NT) {
        int g = idx >> 8, e = (idx >> 4) & 15, l = idx & 15;
        float acc = 0.f;
        #pragma unroll
        for (int r = 0; r < 8; r++) {
            float wp = Wp[g * 128 + r * 16 + e];
            float ws = Ws[g * 128 + r * 16 + e];
            acc += (ws - wp) * Wp[g * 128 + r * 16 + l];
        }
        sM[idx] = acc;
    }
    for (int idx = tid; idx < 4 * 16; idx += NT) {
        int g = idx >> 4, l = idx & 15;
        float acc = 0.f;
        #pragma unroll
        for (int r = 0; r < 8; r++)
            acc += (bs[g * 8 + r] - bp[g * 8 + r]) * Wp[g * 128 + r * 16 + l];
        sC[idx] = acc;
    }
    if (tid < STAGES) mbar_init(bar0 + tid * 8, 1);
    __syncthreads();

    // ---- remainder rows (B % T_ROWS), plain global path ----
    const long long firstRemF4 = (long long)nTiles * TILE_F4 * 1;  // in units below
    if (blockIdx.x == 0) {
        const float4* in4 = (const float4*)base;
        float4* out4 = (float4*)out;
        const long long remStart = (long long)nTiles * T_ROWS * 192;
        const long long totF4 = (long long)B * 192;
        for (long long i = remStart + tid; i < totF4; i += NT) {
            int c4 = (int)(i % 192);
            long long row = i / 192;
            float4 v = in4[i];
            int off, g = region_of(c4, off);
            if (g >= 0) {
                const float4* xb = in4 + row * 192 + start4_of(g);
                float x[16];
                #pragma unroll
                for (int k = 0; k < 4; k++) {
                    float4 t = xb[k];
                    x[4*k] = t.x; x[4*k+1] = t.y; x[4*k+2] = t.z; x[4*k+3] = t.w;
                }
                int q = off * 4;
                float d0 = sC[g*16+q], d1 = sC[g*16+q+1], d2 = sC[g*16+q+2], d3 = sC[g*16+q+3];
                #pragma unroll
                for (int e = 0; e < 16; e++) {
                    float xe = x[e];
                    d0 += sM[(g*16+e)*16+q  ] * xe;
                    d1 += sM[(g*16+e)*16+q+1] * xe;
                    d2 += sM[(g*16+e)*16+q+2] * xe;
                    d3 += sM[(g*16+e)*16+q+3] * xe;
                }
                v.x += d0; v.y += d1; v.z += d2; v.w += d3;
            }
            out4[i] = v;
        }
    }
    (void)firstRemF4;

    // ---- per-thread static chunk geometry (4 chunks per thread) ----
    int c4_[4], rowb_[4], g_[4], q_[4];
    #pragma unroll
    for (int j = 0; j < 4; j++) {
        int chunk = tid + NT * j;          // 0..1535
        int row = chunk / 192;
        int c4 = chunk - row * 192;
        c4_[j] = c4; rowb_[j] = row * 192;
        int off; g_[j] = region_of(c4, off); q_[j] = off * 4;
    }

    // ---- tile count for this block ----
    const int bid = blockIdx.x;
    int count = 0;
    if (bid < nTiles) count = (nTiles - bid + grid - 1) / grid;

    // prologue: fill the pipeline
    if (tid == 0) {
        int pre = count < STAGES ? count : STAGES;
        for (int k = 0; k < pre; k++) {
            long long tile = (long long)bid + (long long)k * grid;
            mbar_expect_tx(bar0 + k * 8, TILE_BYTES);
            bulk_ld(smem_base + (uint32_t)(k * TILE_BYTES), base + tile * TILE_F,
                    TILE_BYTES, bar0 + k * 8);
        }
    }

    const float4* sbuf4base = (const float4*)smem;
    for (int k = 0; k < count; k++) {
        const int s = k % STAGES;
        const int parity = (k / STAGES) & 1;
        mbar_wait(bar0 + s * 8, parity);

        const float4* sb = sbuf4base + s * TILE_F4;
        const long long tile = (long long)bid + (long long)k * grid;
        float4* op = (float4*)out + tile * TILE_F4;

        #pragma unroll
        for (int j = 0; j < 4; j++) {
            const int chunk = tid + NT * j;
            float4 v = sb[chunk];
            const int g = g_[j];
            if (g >= 0) {
                const float4* xb = sb + rowb_[j] + start4_of(g);
                float x[16];
                #pragma unroll
                for (int kk = 0; kk < 4; kk++) {
                    float4 t = xb[kk];
                    x[4*kk] = t.x; x[4*kk+1] = t.y; x[4*kk+2] = t.z; x[4*kk+3] = t.w;
                }
                const int q = q_[j];
                float d0 = sC[g*16+q], d1 = sC[g*16+q+1], d2 = sC[g*16+q+2], d3 = sC[g*16+q+3];
                #pragma unroll
                for (int e = 0; e < 16; e++) {
                    float xe = x[e];
                    d0 += sM[(g*16+e)*16+q  ] * xe;
                    d1 += sM[(g*16+e)*16+q+1] * xe;
                    d2 += sM[(g*16+e)*16+q+2] * xe;
                    d3 += sM[(g*16+e)*16+q+3] * xe;
                }
                v.x += d0; v.y += d1; v.z += d2; v.w += d3;
            }
            __stcs(op + chunk, v);
        }

        __syncthreads();  // all reads of stage s done before refill

        if (tid == 0 && k + STAGES < count) {
            long long nt = (long long)bid + (long long)(k + STAGES) * grid;
            mbar_expect_tx(bar0 + s * 8, TILE_BYTES);
            bulk_ld(smem_base + (uint32_t)(s * TILE_BYTES), base + nt * TILE_F,
                    TILE_BYTES, bar0 + s * 8);
        }
    }
}

extern "C" void kernel_launch(void* const* d_in, const int* in_sizes, int n_in,
                              void* d_out, int out_size)
{
    const float* base = (const float*)d_in[0];  // [1, B, 768]
    const float* Wp   = (const float*)d_in[1];
    const float* bp   = (const float*)d_in[2];
    const float* Ws   = (const float*)d_in[3];
    const float* bs   = (const float*)d_in[4];
    float* out = (float*)d_out;

    const int B = in_sizes[0] / 768;
    const int nTiles = B / T_ROWS;

    int grid = nTiles < MAXGRID ? (nTiles > 0 ? nTiles : 1) : MAXGRID;

    static int configured = 0;
    if (!configured) {
        cudaFuncSetAttribute(minireft_tma,
                             cudaFuncAttributeMaxDynamicSharedMemorySize, SM_BYTES);
        configured = 1;
    }

    minireft_tma<<<grid, NT, SM_BYTES>>>(base, out, Wp, bp, Ws, bs, B, nTiles, grid);
}